// round 15
// baseline (speedup 1.0000x reference)
#include <cuda_runtime.h>
#include <cuda_bf16.h>
#include <math.h>
#include <stdint.h>

#define D      80
#define DB     96           // padded fp8 bytes per row (3 k-steps of 32)
#define DW     24           // 32-bit words per padded row
#define SROW   112          // smem row stride: (28*r+lm)%32 distinct -> conflict-free
#define NMAX   8192
#define TILE   128
#define NCHUNK 2            // grid = 64*2 = 128 blocks -> single wave on 148 SMs
#define KS     3            // k-steps of 32 (K padded 80 -> 96 with zeros)

// fp8(e4m3) normalized matrices, row-major [N][96]; A pre-scaled by log2(e).
__device__ __align__(16) uint8_t g_A8[NMAX * DB];
__device__ __align__(16) uint8_t g_B8[NMAX * DB];
__device__ float g_pos[NMAX];                            // exact fp32 diagonal sims
__device__ float g_psum[(NMAX / TILE) * NCHUNK * TILE];

__device__ __forceinline__ float ex2f(float x) {
    float y;
    asm("ex2.approx.f32 %0, %1;" : "=f"(y) : "f"(x));
    return y;
}

// pack 4 floats -> 4 e4m3 bytes (byte0 = f0); cvt packs op A into the HIGH byte
__device__ __forceinline__ uint32_t pack_e4m3x4(float f0, float f1, float f2, float f3) {
    unsigned short lo, hi;
    asm("cvt.rn.satfinite.e4m3x2.f32 %0, %1, %2;" : "=h"(lo) : "f"(f1), "f"(f0));
    asm("cvt.rn.satfinite.e4m3x2.f32 %0, %1, %2;" : "=h"(hi) : "f"(f3), "f"(f2));
    return ((uint32_t)hi << 16) | (uint32_t)lo;
}

// ---------------------------------------------------------------------------
// Kernel 1: fused L2-normalize -> fp8 (A scaled by log2e) + exact fp32 diag.
// Warp-per-row: block = 256 (8 rows), grid = N/8. No smem, no barriers.
// ---------------------------------------------------------------------------
__global__ void mmi_prep(const float* __restrict__ o,
                         const float* __restrict__ t, int N) {
    const int wid  = threadIdx.x >> 5;
    const int lane = threadIdx.x & 31;
    const int row  = blockIdx.x * 8 + wid;

    float4 xo = make_float4(0.f, 0.f, 0.f, 0.f);
    float4 xt = make_float4(0.f, 0.f, 0.f, 0.f);
    if (lane < D / 4) {
        xo = ((const float4*)o)[row * (D / 4) + lane];
        xt = ((const float4*)t)[row * (D / 4) + lane];
    }
    float oo = xo.x * xo.x + xo.y * xo.y + xo.z * xo.z + xo.w * xo.w;
    float tt = xt.x * xt.x + xt.y * xt.y + xt.z * xt.z + xt.w * xt.w;
    float ot = xo.x * xt.x + xo.y * xt.y + xo.z * xt.z + xo.w * xt.w;
#pragma unroll
    for (int off = 16; off > 0; off >>= 1) {
        oo += __shfl_xor_sync(0xffffffffu, oo, off);
        tt += __shfl_xor_sync(0xffffffffu, tt, off);
        ot += __shfl_xor_sync(0xffffffffu, ot, off);
    }
    const float no = fmaxf(sqrtf(oo), 1e-12f);
    const float nt = fmaxf(sqrtf(tt), 1e-12f);
    const float sa = 1.4426950408889634f / no;   // log2(e)/||o||
    const float sb = 1.0f / nt;

    if (lane < DW) {
        uint32_t wa = 0u, wb = 0u;
        if (lane < D / 4) {
            wa = pack_e4m3x4(xo.x * sa, xo.y * sa, xo.z * sa, xo.w * sa);
            wb = pack_e4m3x4(xt.x * sb, xt.y * sb, xt.z * sb, xt.w * sb);
        }
        ((uint32_t*)g_A8)[row * DW + lane] = wa;
        ((uint32_t*)g_B8)[row * DW + lane] = wb;
    }
    if (lane == 0) g_pos[row] = ot / (no * nt);
}

// ---------------------------------------------------------------------------
// mma.sync m16n8k32 e4m3 (base sm_89+ feature — survives compute_103 target)
// ---------------------------------------------------------------------------
__device__ __forceinline__ void mma_fp8(float c[4], const unsigned a[4],
                                        const unsigned b0, const unsigned b1) {
    asm volatile(
        "mma.sync.aligned.m16n8k32.row.col.f32.e4m3.e4m3.f32 "
        "{%0,%1,%2,%3}, {%4,%5,%6,%7}, {%8,%9}, {%0,%1,%2,%3};"
        : "+f"(c[0]), "+f"(c[1]), "+f"(c[2]), "+f"(c[3])
        : "r"(a[0]), "r"(a[1]), "r"(a[2]), "r"(a[3]), "r"(b0), "r"(b1));
}

// ---------------------------------------------------------------------------
// Kernel 2: fused fp8 sim-GEMM + exp2 row-sums. Double-buffered sB, one BAR
// per tile (proven 47.9us structure). block = 256 (8 warps 2x4), warp 64x32.
// ---------------------------------------------------------------------------
__global__ void __launch_bounds__(256, 1)
mmi_main(int N) {
    __shared__ __align__(16) char sA [TILE * SROW];   // 14336 B
    __shared__ __align__(16) char sB0[TILE * SROW];   // 14336 B
    __shared__ __align__(16) char sB1[TILE * SROW];   // 14336 B
    __shared__ float sSums[TILE * 4];                 // [row][warpN]

    const int tid   = threadIdx.x;
    const int wid   = tid >> 5;
    const int lane  = tid & 31;
    const int l4    = lane >> 2;
    const int lm    = lane & 3;
    const int warpM = wid >> 2;
    const int warpN = wid & 3;
    const int wr    = warpM * 64;

    const int rt = blockIdx.x / NCHUNK;
    const int ch = blockIdx.x - rt * NCHUNK;
    const int rb = rt * TILE;
    const int nT = (N / TILE) / NCHUNK;          // 32
    const int colBeg = ch * nT * TILE;

    // staging: 128 rows x 96 B = 768 uint4; 3 per thread
    int srow[3], sc16[3];
#pragma unroll
    for (int j = 0; j < 3; j++) {
        const int v = tid + j * 256;
        srow[j] = v / 6;
        sc16[j] = (v - srow[j] * 6) * 16;
    }

    // stage A tile + B tile 0
#pragma unroll
    for (int j = 0; j < 3; j++) {
        *(uint4*)(sA  + srow[j] * SROW + sc16[j]) =
            *(const uint4*)&g_A8[(rb + srow[j]) * DB + sc16[j]];
        *(uint4*)(sB0 + srow[j] * SROW + sc16[j]) =
            *(const uint4*)&g_B8[(colBeg + srow[j]) * DB + sc16[j]];
    }
    __syncthreads();

    // hoist all A fragments (3 k-steps x 4 m-frags x 4 regs) — col-tile invariant
    unsigned afr[KS][4][4];
#pragma unroll
    for (int ks = 0; ks < KS; ks++) {
#pragma unroll
        for (int i = 0; i < 4; i++) {
            const int r0 = wr + i * 16 + l4;
            const int k0 = ks * 32 + lm * 4;
            afr[ks][i][0] = *(const unsigned*)(sA + r0 * SROW + k0);
            afr[ks][i][1] = *(const unsigned*)(sA + (r0 + 8) * SROW + k0);
            afr[ks][i][2] = *(const unsigned*)(sA + r0 * SROW + k0 + 16);
            afr[ks][i][3] = *(const unsigned*)(sA + (r0 + 8) * SROW + k0 + 16);
        }
    }

    float rowsum[8];
#pragma unroll
    for (int p = 0; p < 8; p++) rowsum[p] = 0.f;

    uint4 pf[3];
    for (int tt = 0; tt < nT; tt++) {
        const char* cur = (tt & 1) ? sB1 : sB0;
        char*       nxt = (tt & 1) ? sB0 : sB1;
        const bool more = (tt + 1 < nT);

        // issue next tile's global loads first — latency hides under MMAs
        if (more) {
            const int nb = colBeg + (tt + 1) * TILE;
#pragma unroll
            for (int j = 0; j < 3; j++)
                pf[j] = *(const uint4*)&g_B8[(nb + srow[j]) * DB + sc16[j]];
        }

        float c4[4][4][4];
#pragma unroll
        for (int i = 0; i < 4; i++)
#pragma unroll
            for (int j = 0; j < 4; j++)
#pragma unroll
                for (int q = 0; q < 4; q++) c4[i][j][q] = 0.f;

#pragma unroll
        for (int ks = 0; ks < KS; ks++) {
            unsigned b0[4], b1[4];
#pragma unroll
            for (int j = 0; j < 4; j++) {
                const int n0 = warpN * 32 + j * 8 + l4;
                const int k0 = ks * 32 + lm * 4;
                b0[j] = *(const unsigned*)(cur + n0 * SROW + k0);
                b1[j] = *(const unsigned*)(cur + n0 * SROW + k0 + 16);
            }
#pragma unroll
            for (int i = 0; i < 4; i++)
#pragma unroll
                for (int j = 0; j < 4; j++)
                    mma_fp8(c4[i][j], afr[ks][i], b0[j], b1[j]);
        }

        // c4 holds log2(e)*sim -> exp via raw EX2
#pragma unroll
        for (int i = 0; i < 4; i++) {
            float s01 = 0.f, s23 = 0.f;
#pragma unroll
            for (int j = 0; j < 4; j++) {
                s01 += ex2f(c4[i][j][0]) + ex2f(c4[i][j][1]);
                s23 += ex2f(c4[i][j][2]) + ex2f(c4[i][j][3]);
            }
            rowsum[2 * i]     += s01;   // row wr + i*16 + l4
            rowsum[2 * i + 1] += s23;   // row wr + i*16 + l4 + 8
        }

        // store next tile into the released buffer; single barrier per tile
        if (more) {
#pragma unroll
            for (int j = 0; j < 3; j++)
                *(uint4*)(nxt + srow[j] * SROW + sc16[j]) = pf[j];
        }
        __syncthreads();
    }

    // reduce over lm (disjoint column pairs of the same rows)
#pragma unroll
    for (int p = 0; p < 8; p++) {
        rowsum[p] += __shfl_xor_sync(0xffffffffu, rowsum[p], 1);
        rowsum[p] += __shfl_xor_sync(0xffffffffu, rowsum[p], 2);
    }
    if (lm == 0) {
#pragma unroll
        for (int p = 0; p < 8; p++) {
            const int r = wr + (p >> 1) * 16 + l4 + (p & 1) * 8;
            sSums[r * 4 + warpN] = rowsum[p];
        }
    }
    __syncthreads();

    if (tid < TILE) {
        const float tot = sSums[tid * 4 + 0] + sSums[tid * 4 + 1] +
                          sSums[tid * 4 + 2] + sSums[tid * 4 + 3];
        g_psum[blockIdx.x * TILE + tid] = tot;
    }
}

// ---------------------------------------------------------------------------
// Kernel 3: loss = mean( log(sum_chunks) - pos ). 1 block x 512 threads.
// ---------------------------------------------------------------------------
__global__ void mmi_finalize(float* __restrict__ out, int N) {
    __shared__ float s[512];
    const int tid = threadIdx.x;
    float acc = 0.f;
    for (int r = tid; r < N; r += 512) {
        const int rt = r / TILE;
        const int ri = r - rt * TILE;
        float tot = 0.f;
#pragma unroll
        for (int c = 0; c < NCHUNK; c++)
            tot += g_psum[(rt * NCHUNK + c) * TILE + ri];
        acc += logf(tot) - g_pos[r];
    }
    s[tid] = acc;
    __syncthreads();
#pragma unroll
    for (int off = 256; off > 0; off >>= 1) {
        if (tid < off) s[tid] += s[tid + off];
        __syncthreads();
    }
    if (tid == 0) out[0] = s[0] / (float)N;
}

// ---------------------------------------------------------------------------
extern "C" void kernel_launch(void* const* d_in, const int* in_sizes, int n_in,
                              void* d_out, int out_size) {
    const float* o = (const float*)d_in[0];   // mel_outputs [B,T,D]
    const float* t = (const float*)d_in[1];   // mel_targets [B,T,D]
    float* out = (float*)d_out;

    const int N = in_sizes[0] / D;            // 8192

    mmi_prep<<<N / 8, 256>>>(o, t, N);
    mmi_main<<<(N / TILE) * NCHUNK, 256>>>(N);
    mmi_finalize<<<1, 512>>>(out, N);
}